// round 8
// baseline (speedup 1.0000x reference)
#include <cuda_runtime.h>
#include <cuda_bf16.h>
#include <math.h>

// Problem constants (fixed shapes)
#define NN   131072     // nodes
#define GG   1024       // graphs
#define NPGG 128        // nodes per graph
#define EE   4194304    // edges per branch
#define DD   128        // input feature dim
#define LAT  32         // per-layer output dim
#define CATW 288        // 3 branches * 3 layers * 32
#define HIDW 128

// Output layout (float32): logits [G,2] | loss [1] | acc [1] | feature [G,128]
#define OFF_LOSS (GG * 2)
#define OFF_ACC  (GG * 2 + 1)
#define OFF_FEAT (GG * 2 + 2)

// -------- scratch (static device globals; no allocation allowed) --------
__device__ float g_S  [NN * LAT];   // (h@W)*dis per node
__device__ float g_AGG[NN * LAT];   // scatter accumulator
__device__ float g_H  [NN * LAT];   // layer output (input to next layer)
__device__ float g_DIS[NN];         // rsqrt(deg+1)
__device__ int   g_DEG[NN];         // in-degree
__device__ float g_CAT[GG * CATW];  // readout concat buffer

// ---------------------------------------------------------------------------
__global__ void k_zero4(float4* p, int n4) {
    int i = blockIdx.x * blockDim.x + threadIdx.x;
    if (i < n4) p[i] = make_float4(0.f, 0.f, 0.f, 0.f);
}

__global__ void k_deg(const int* __restrict__ ei, int* __restrict__ deg) {
    int e = blockIdx.x * blockDim.x + threadIdx.x;
    if (e < EE) atomicAdd(&deg[ei[EE + e]], 1);
}

__global__ void k_dis(const int* __restrict__ deg, float* __restrict__ dis) {
    int n = blockIdx.x * blockDim.x + threadIdx.x;
    if (n < NN) dis[n] = rsqrtf((float)deg[n] + 1.0f);
}

// S[n,:] = (x[n,:] @ W) * dis[n]   (din = 128, dout = 32)
__global__ __launch_bounds__(256) void k_gemm128(
    const float* __restrict__ x, const float* __restrict__ W,
    const float* __restrict__ dis, float* __restrict__ S)
{
    __shared__ float Ws[DD * LAT];  // 16 KB
    int tid = threadIdx.x;
    for (int i = tid; i < DD * LAT; i += 256) Ws[i] = W[i];
    __syncthreads();

    int n = blockIdx.x * 256 + tid;
    const float4* xr = (const float4*)(x + (size_t)n * DD);
    float acc[LAT];
#pragma unroll
    for (int j = 0; j < LAT; ++j) acc[j] = 0.f;

    for (int k4 = 0; k4 < DD / 4; ++k4) {
        float4 xv = xr[k4];
        const float* wr = Ws + k4 * 4 * LAT;
#pragma unroll
        for (int j = 0; j < LAT; ++j) {
            float a = acc[j];
            a = fmaf(xv.x, wr[j],            a);
            a = fmaf(xv.y, wr[LAT + j],      a);
            a = fmaf(xv.z, wr[2 * LAT + j],  a);
            a = fmaf(xv.w, wr[3 * LAT + j],  a);
            acc[j] = a;
        }
    }
    float d = dis[n];
    float4* Sr = (float4*)(S + (size_t)n * LAT);
#pragma unroll
    for (int j4 = 0; j4 < LAT / 4; ++j4)
        Sr[j4] = make_float4(acc[j4 * 4] * d, acc[j4 * 4 + 1] * d,
                             acc[j4 * 4 + 2] * d, acc[j4 * 4 + 3] * d);
}

// S[n,:] = (h[n,:] @ W) * dis[n]   (din = 32, dout = 32)
__global__ __launch_bounds__(256) void k_gemm32(
    const float* __restrict__ h, const float* __restrict__ W,
    const float* __restrict__ dis, float* __restrict__ S)
{
    __shared__ float Ws[LAT * LAT];  // 4 KB
    int tid = threadIdx.x;
    for (int i = tid; i < LAT * LAT; i += 256) Ws[i] = W[i];
    __syncthreads();

    int n = blockIdx.x * 256 + tid;
    const float4* hr = (const float4*)(h + (size_t)n * LAT);
    float xv[LAT];
#pragma unroll
    for (int k4 = 0; k4 < LAT / 4; ++k4) {
        float4 v = hr[k4];
        xv[k4 * 4] = v.x; xv[k4 * 4 + 1] = v.y; xv[k4 * 4 + 2] = v.z; xv[k4 * 4 + 3] = v.w;
    }
    float acc[LAT];
#pragma unroll
    for (int j = 0; j < LAT; ++j) acc[j] = 0.f;
    for (int k = 0; k < LAT; ++k) {
        float xk = xv[k];
        const float* wr = Ws + k * LAT;
#pragma unroll
        for (int j = 0; j < LAT; ++j) acc[j] = fmaf(xk, wr[j], acc[j]);
    }
    float d = dis[n];
    float4* Sr = (float4*)(S + (size_t)n * LAT);
#pragma unroll
    for (int j4 = 0; j4 < LAT / 4; ++j4)
        Sr[j4] = make_float4(acc[j4 * 4] * d, acc[j4 * 4 + 1] * d,
                             acc[j4 * 4 + 2] * d, acc[j4 * 4 + 3] * d);
}

// AGG[dst,:] += S[src,:]  — 8 threads per edge, each one float4 reduction
__device__ __forceinline__ void red_add_v4(float* addr, float4 v) {
    asm volatile("red.global.add.v4.f32 [%0], {%1, %2, %3, %4};"
                 :: "l"(addr), "f"(v.x), "f"(v.y), "f"(v.z), "f"(v.w)
                 : "memory");
}

__global__ void k_scatter(const int* __restrict__ ei,
                          const float* __restrict__ S, float* __restrict__ AGG)
{
    int idx = blockIdx.x * blockDim.x + threadIdx.x;   // EE*8 = 33.5M < 2^31
    int e = idx >> 3;
    int c = idx & 7;
    if (e < EE) {
        int src = ei[e];
        int dst = ei[EE + e];
        float4 v = ((const float4*)S)[(size_t)src * 8 + c];
        red_add_v4(AGG + ((size_t)dst * LAT + c * 4), v);
    }
}

// H[n,:] = tanh(dis[n]*(AGG[n,:] + S[n,:]) + b);  also write selected rows to CAT
__global__ void k_combine(const float* __restrict__ AGG, const float* __restrict__ S,
                          const float* __restrict__ dis, const float* __restrict__ bias,
                          float* __restrict__ H, float* __restrict__ CAT, int catBase)
{
    int idx = blockIdx.x * blockDim.x + threadIdx.x;   // NN*8
    if (idx >= NN * 8) return;
    int n = idx >> 3;
    int c = idx & 7;
    float4 a = ((const float4*)AGG)[idx];
    float4 s = ((const float4*)S)[idx];
    float4 b = ((const float4*)bias)[c];
    float d = dis[n];
    float4 o;
    o.x = tanhf(d * (a.x + s.x) + b.x);
    o.y = tanhf(d * (a.y + s.y) + b.y);
    o.z = tanhf(d * (a.z + s.z) + b.z);
    o.w = tanhf(d * (a.w + s.w) + b.w);
    ((float4*)H)[idx] = o;
    if ((n & (NPGG - 1)) == 0) {
        int g = n >> 7;
        float4* cr = (float4*)(CAT + (size_t)g * CATW + catBase + c * 4);
        *cr = o;
    }
}

__global__ void k_init_out(float* out) {
    out[OFF_LOSS] = 0.f;
    out[OFF_ACC]  = 0.f;
}

// Head: per graph, hidden = cat@W1 + b1; feature = hidden; h = relu(hidden);
// logits = log_softmax(h@W2 + b2); loss/acc accumulated atomically.
__global__ __launch_bounds__(HIDW) void k_head(
    const float* __restrict__ CAT, const float* __restrict__ W1,
    const float* __restrict__ b1, const float* __restrict__ W2,
    const float* __restrict__ b2, const int* __restrict__ y,
    float* __restrict__ out)
{
    int g = blockIdx.x;
    int tid = threadIdx.x;
    __shared__ float cr[CATW];
    for (int i = tid; i < CATW; i += HIDW) cr[i] = CAT[(size_t)g * CATW + i];
    __syncthreads();

    float acc = b1[tid];
    for (int k = 0; k < CATW; ++k)
        acc = fmaf(cr[k], W1[(size_t)k * HIDW + tid], acc);

    out[OFF_FEAT + (size_t)g * HIDW + tid] = acc;     // feature = pre-relu hidden

    float h = fmaxf(acc, 0.f);
    float p0 = h * W2[tid * 2];
    float p1 = h * W2[tid * 2 + 1];
#pragma unroll
    for (int off = 16; off > 0; off >>= 1) {
        p0 += __shfl_down_sync(0xffffffffu, p0, off);
        p1 += __shfl_down_sync(0xffffffffu, p1, off);
    }
    __shared__ float r0s[4], r1s[4];
    int wid = tid >> 5;
    if ((tid & 31) == 0) { r0s[wid] = p0; r1s[wid] = p1; }
    __syncthreads();
    if (tid == 0) {
        float l0 = r0s[0] + r0s[1] + r0s[2] + r0s[3] + b2[0];
        float l1 = r1s[0] + r1s[1] + r1s[2] + r1s[3] + b2[1];
        float m = fmaxf(l0, l1);
        float lse = m + logf(expf(l0 - m) + expf(l1 - m));
        float ls0 = l0 - lse, ls1 = l1 - lse;
        out[g * 2]     = ls0;
        out[g * 2 + 1] = ls1;
        int yy = y[g];
        atomicAdd(&out[OFF_LOSS], -(yy ? ls1 : ls0) * (1.0f / GG));
        int pred = (l1 > l0) ? 1 : 0;
        if (pred == yy) atomicAdd(&out[OFF_ACC], 1.0f / GG);
    }
}

// ---------------------------------------------------------------------------
extern "C" void kernel_launch(void* const* d_in, const int* in_sizes, int n_in,
                              void* d_out, int out_size)
{
    (void)in_sizes; (void)n_in; (void)out_size;

    float *S, *AGG, *H, *DIS, *CAT;
    int* DEG;
    cudaGetSymbolAddress((void**)&S,   g_S);
    cudaGetSymbolAddress((void**)&AGG, g_AGG);
    cudaGetSymbolAddress((void**)&H,   g_H);
    cudaGetSymbolAddress((void**)&DIS, g_DIS);
    cudaGetSymbolAddress((void**)&CAT, g_CAT);
    cudaGetSymbolAddress((void**)&DEG, g_DEG);

    const int*   y   = (const int*)d_in[9];
    const float* Wc[3] = { (const float*)d_in[10], (const float*)d_in[12], (const float*)d_in[14] };
    const float* bc[3] = { (const float*)d_in[11], (const float*)d_in[13], (const float*)d_in[15] };
    const float* W1 = (const float*)d_in[16];
    const float* b1 = (const float*)d_in[17];
    const float* W2 = (const float*)d_in[18];
    const float* b2 = (const float*)d_in[19];
    float* out = (float*)d_out;

    k_init_out<<<1, 1>>>(out);

    const int ZT = 256;
    for (int b = 0; b < 3; ++b) {
        const float* x  = (const float*)d_in[3 * b];
        const int*   ei = (const int*)  d_in[3 * b + 1];

        // degree + normalization
        k_zero4<<<(NN / 4 + ZT - 1) / ZT, ZT>>>((float4*)DEG, NN / 4);
        k_deg<<<EE / 256, 256>>>(ei, DEG);
        k_dis<<<NN / 256, 256>>>(DEG, DIS);

        for (int l = 0; l < 3; ++l) {
            if (l == 0) k_gemm128<<<NN / 256, 256>>>(x, Wc[0], DIS, S);
            else        k_gemm32 <<<NN / 256, 256>>>(H, Wc[l], DIS, S);

            k_zero4<<<(NN * 8 + ZT - 1) / ZT, ZT>>>((float4*)AGG, NN * 8);
            k_scatter<<<(EE * 8) / 256, 256>>>(ei, S, AGG);
            k_combine<<<(NN * 8) / 256, 256>>>(AGG, S, DIS, bc[l], H, CAT,
                                               b * 96 + l * 32);
        }
    }

    k_head<<<GG, HIDW>>>(CAT, W1, b1, W2, b2, y, out);
}

// round 9
// speedup vs baseline: 1.2383x; 1.2383x over previous
#include <cuda_runtime.h>
#include <cuda_bf16.h>
#include <math.h>

// Problem constants (fixed shapes)
#define NN   131072     // nodes
#define GG   1024       // graphs
#define NPGG 128        // nodes per graph
#define EE   4194304    // edges per branch
#define DD   128        // input feature dim
#define LAT  32         // per-layer output dim
#define CATW 288        // 3 branches * 3 layers * 32
#define HIDW 128

// Output layout (float32): logits [G,2] | loss [1] | acc [1] | feature [G,128]
#define OFF_LOSS (GG * 2)
#define OFF_ACC  (GG * 2 + 1)
#define OFF_FEAT (GG * 2 + 2)

// -------- scratch (static device globals; no allocation allowed) --------
__device__ float g_SA [NN * LAT];   // S ping
__device__ float g_SB [NN * LAT];   // S pong
__device__ float g_DIS[NN];         // rsqrt(deg+1)
__device__ int   g_DEG[NN];         // in-degree
__device__ int   g_ROW[NN];         // CSR row offsets (exclusive prefix of deg)
__device__ int   g_CUR[NN];         // fill cursors
__device__ int   g_CSR[EE];         // CSR column (src) indices
__device__ int   g_BSUM[512];       // scan block sums
__device__ int   g_BOFF[512];       // scan block offsets
__device__ float g_CAT[GG * CATW];  // readout concat buffer

// ---------------------------------------------------------------------------
__global__ void k_zero4(float4* p, int n4) {
    int i = blockIdx.x * blockDim.x + threadIdx.x;
    if (i < n4) p[i] = make_float4(0.f, 0.f, 0.f, 0.f);
}

// in-degree, 4 edges per thread
__global__ void k_deg(const int* __restrict__ ei, int* __restrict__ deg) {
    int i = blockIdx.x * blockDim.x + threadIdx.x;     // EE/4 threads
    int4 d = ((const int4*)(ei + EE))[i];
    atomicAdd(&deg[d.x], 1);
    atomicAdd(&deg[d.y], 1);
    atomicAdd(&deg[d.z], 1);
    atomicAdd(&deg[d.w], 1);
}

__global__ void k_dis(const int* __restrict__ deg, float* __restrict__ dis) {
    int n = blockIdx.x * blockDim.x + threadIdx.x;
    if (n < NN) dis[n] = rsqrtf((float)deg[n] + 1.0f);
}

// ---- 3-phase exclusive scan of deg -> row (NN = 512 blocks * 256) ----
__global__ __launch_bounds__(256) void k_scan1(const int* __restrict__ deg,
                                               int* __restrict__ row,
                                               int* __restrict__ bsum) {
    __shared__ int sh[256];
    int t = threadIdx.x;
    int i = blockIdx.x * 256 + t;
    int v = deg[i];
    sh[t] = v;
    __syncthreads();
    for (int off = 1; off < 256; off <<= 1) {
        int x = (t >= off) ? sh[t - off] : 0;
        __syncthreads();
        sh[t] += x;
        __syncthreads();
    }
    row[i] = sh[t] - v;               // exclusive within block
    if (t == 255) bsum[blockIdx.x] = sh[t];
}

__global__ __launch_bounds__(512) void k_scan2(const int* __restrict__ bsum,
                                               int* __restrict__ boff) {
    __shared__ int sh[512];
    int t = threadIdx.x;
    int v = bsum[t];
    sh[t] = v;
    __syncthreads();
    for (int off = 1; off < 512; off <<= 1) {
        int x = (t >= off) ? sh[t - off] : 0;
        __syncthreads();
        sh[t] += x;
        __syncthreads();
    }
    boff[t] = sh[t] - v;              // exclusive
}

__global__ __launch_bounds__(256) void k_scan3(int* __restrict__ row,
                                               const int* __restrict__ boff) {
    int i = blockIdx.x * 256 + threadIdx.x;
    row[i] += boff[blockIdx.x];
}

// fill CSR: csr[row[dst] + cursor[dst]++] = src  (4 edges/thread)
__global__ void k_fill(const int* __restrict__ ei, const int* __restrict__ row,
                       int* __restrict__ cur, int* __restrict__ csr) {
    int i = blockIdx.x * blockDim.x + threadIdx.x;     // EE/4 threads
    int4 s4 = ((const int4*)ei)[i];
    int4 d4 = ((const int4*)(ei + EE))[i];
    int p;
    p = row[d4.x] + atomicAdd(&cur[d4.x], 1); csr[p] = s4.x;
    p = row[d4.y] + atomicAdd(&cur[d4.y], 1); csr[p] = s4.y;
    p = row[d4.z] + atomicAdd(&cur[d4.z], 1); csr[p] = s4.z;
    p = row[d4.w] + atomicAdd(&cur[d4.w], 1); csr[p] = s4.w;
}

// S[n,:] = (x[n,:] @ W) * dis[n]   (din = 128, dout = 32)
__global__ __launch_bounds__(256) void k_gemm128(
    const float* __restrict__ x, const float* __restrict__ W,
    const float* __restrict__ dis, float* __restrict__ S)
{
    __shared__ float Ws[DD * LAT];  // 16 KB
    int tid = threadIdx.x;
    for (int i = tid; i < DD * LAT; i += 256) Ws[i] = W[i];
    __syncthreads();

    int n = blockIdx.x * 256 + tid;
    const float4* xr = (const float4*)(x + (size_t)n * DD);
    float acc[LAT];
#pragma unroll
    for (int j = 0; j < LAT; ++j) acc[j] = 0.f;

    for (int k4 = 0; k4 < DD / 4; ++k4) {
        float4 xv = xr[k4];
        const float* wr = Ws + k4 * 4 * LAT;
#pragma unroll
        for (int j = 0; j < LAT; ++j) {
            float a = acc[j];
            a = fmaf(xv.x, wr[j],            a);
            a = fmaf(xv.y, wr[LAT + j],      a);
            a = fmaf(xv.z, wr[2 * LAT + j],  a);
            a = fmaf(xv.w, wr[3 * LAT + j],  a);
            acc[j] = a;
        }
    }
    float d = dis[n];
    float4* Sr = (float4*)(S + (size_t)n * LAT);
#pragma unroll
    for (int j4 = 0; j4 < LAT / 4; ++j4)
        Sr[j4] = make_float4(acc[j4 * 4] * d, acc[j4 * 4 + 1] * d,
                             acc[j4 * 4 + 2] * d, acc[j4 * 4 + 3] * d);
}

// Fused: gather neighbors from Sin (CSR), combine (tanh), write CAT row for
// selected nodes, and (if FUSE) compute next layer's S = (o @ Wnext) * dis
// entirely in-register via warp shuffles. Warp per node, lane = channel.
template<int FUSE>
__global__ __launch_bounds__(256) void k_gather(
    const int* __restrict__ row, const int* __restrict__ deg,
    const int* __restrict__ csr, const float* __restrict__ Sin,
    const float* __restrict__ dis, const float* __restrict__ bias,
    const float* __restrict__ Wnext, float* __restrict__ Snext,
    float* __restrict__ CAT, int catBase)
{
    __shared__ float Ws[LAT * LAT];
    int tid = threadIdx.x;
    if (FUSE) {
        for (int i = tid; i < LAT * LAT; i += 256) Ws[i] = Wnext[i];
        __syncthreads();
    }
    int lane = tid & 31;
    int n = blockIdx.x * 8 + (tid >> 5);

    int start = row[n];
    int end   = start + deg[n];

    float acc = Sin[(size_t)n * LAT + lane];   // self-loop term (pre-scaled)
    for (int base = start; base < end; base += 32) {
        int m = end - base;
        if (m > 32) m = 32;
        int idx = 0;
        if (base + lane < end) idx = csr[base + lane];
#pragma unroll 4
        for (int k = 0; k < m; ++k) {
            int s = __shfl_sync(0xffffffffu, idx, k);
            acc += Sin[(size_t)s * LAT + lane];
        }
    }

    float d = dis[n];
    float o = tanhf(d * acc + bias[lane]);

    if ((n & (NPGG - 1)) == 0)
        CAT[(size_t)(n >> 7) * CATW + catBase + lane] = o;

    if (FUSE) {
        float sacc = 0.f;
#pragma unroll
        for (int k = 0; k < LAT; ++k) {
            float ok = __shfl_sync(0xffffffffu, o, k);
            sacc = fmaf(ok, Ws[k * LAT + lane], sacc);
        }
        Snext[(size_t)n * LAT + lane] = sacc * d;
    }
}

__global__ void k_init_out(float* out) {
    out[OFF_LOSS] = 0.f;
    out[OFF_ACC]  = 0.f;
}

// Head: per graph, hidden = cat@W1 + b1; feature = hidden; h = relu(hidden);
// logits = log_softmax(h@W2 + b2); loss/acc accumulated atomically.
__global__ __launch_bounds__(HIDW) void k_head(
    const float* __restrict__ CAT, const float* __restrict__ W1,
    const float* __restrict__ b1, const float* __restrict__ W2,
    const float* __restrict__ b2, const int* __restrict__ y,
    float* __restrict__ out)
{
    int g = blockIdx.x;
    int tid = threadIdx.x;
    __shared__ float cr[CATW];
    for (int i = tid; i < CATW; i += HIDW) cr[i] = CAT[(size_t)g * CATW + i];
    __syncthreads();

    float acc = b1[tid];
    for (int k = 0; k < CATW; ++k)
        acc = fmaf(cr[k], W1[(size_t)k * HIDW + tid], acc);

    out[OFF_FEAT + (size_t)g * HIDW + tid] = acc;     // feature = pre-relu hidden

    float h = fmaxf(acc, 0.f);
    float p0 = h * W2[tid * 2];
    float p1 = h * W2[tid * 2 + 1];
#pragma unroll
    for (int off = 16; off > 0; off >>= 1) {
        p0 += __shfl_down_sync(0xffffffffu, p0, off);
        p1 += __shfl_down_sync(0xffffffffu, p1, off);
    }
    __shared__ float r0s[4], r1s[4];
    int wid = tid >> 5;
    if ((tid & 31) == 0) { r0s[wid] = p0; r1s[wid] = p1; }
    __syncthreads();
    if (tid == 0) {
        float l0 = r0s[0] + r0s[1] + r0s[2] + r0s[3] + b2[0];
        float l1 = r1s[0] + r1s[1] + r1s[2] + r1s[3] + b2[1];
        float m = fmaxf(l0, l1);
        float lse = m + logf(expf(l0 - m) + expf(l1 - m));
        float ls0 = l0 - lse, ls1 = l1 - lse;
        out[g * 2]     = ls0;
        out[g * 2 + 1] = ls1;
        int yy = y[g];
        atomicAdd(&out[OFF_LOSS], -(yy ? ls1 : ls0) * (1.0f / GG));
        int pred = (l1 > l0) ? 1 : 0;
        if (pred == yy) atomicAdd(&out[OFF_ACC], 1.0f / GG);
    }
}

// ---------------------------------------------------------------------------
extern "C" void kernel_launch(void* const* d_in, const int* in_sizes, int n_in,
                              void* d_out, int out_size)
{
    (void)in_sizes; (void)n_in; (void)out_size;

    float *SA, *SB, *DIS, *CAT;
    int *DEG, *ROW, *CUR, *CSR, *BSUM, *BOFF;
    cudaGetSymbolAddress((void**)&SA,   g_SA);
    cudaGetSymbolAddress((void**)&SB,   g_SB);
    cudaGetSymbolAddress((void**)&DIS,  g_DIS);
    cudaGetSymbolAddress((void**)&CAT,  g_CAT);
    cudaGetSymbolAddress((void**)&DEG,  g_DEG);
    cudaGetSymbolAddress((void**)&ROW,  g_ROW);
    cudaGetSymbolAddress((void**)&CUR,  g_CUR);
    cudaGetSymbolAddress((void**)&CSR,  g_CSR);
    cudaGetSymbolAddress((void**)&BSUM, g_BSUM);
    cudaGetSymbolAddress((void**)&BOFF, g_BOFF);

    const int*   y   = (const int*)d_in[9];
    const float* Wc[3] = { (const float*)d_in[10], (const float*)d_in[12], (const float*)d_in[14] };
    const float* bc[3] = { (const float*)d_in[11], (const float*)d_in[13], (const float*)d_in[15] };
    const float* W1 = (const float*)d_in[16];
    const float* b1 = (const float*)d_in[17];
    const float* W2 = (const float*)d_in[18];
    const float* b2 = (const float*)d_in[19];
    float* out = (float*)d_out;

    k_init_out<<<1, 1>>>(out);

    const int ZT = 256;
    for (int b = 0; b < 3; ++b) {
        const float* x  = (const float*)d_in[3 * b];
        const int*   ei = (const int*)  d_in[3 * b + 1];

        // ---- CSR build: degree -> scan -> fill ----
        k_zero4<<<(NN / 4 + ZT - 1) / ZT, ZT>>>((float4*)DEG, NN / 4);
        k_zero4<<<(NN / 4 + ZT - 1) / ZT, ZT>>>((float4*)CUR, NN / 4);
        k_deg<<<EE / 4 / 256, 256>>>(ei, DEG);
        k_dis<<<NN / 256, 256>>>(DEG, DIS);
        k_scan1<<<512, 256>>>(DEG, ROW, BSUM);
        k_scan2<<<1, 512>>>(BSUM, BOFF);
        k_scan3<<<512, 256>>>(ROW, BOFF);
        k_fill<<<EE / 4 / 256, 256>>>(ei, ROW, CUR, CSR);

        // ---- layer 0 input GEMM (din=128) ----
        k_gemm128<<<NN / 256, 256>>>(x, Wc[0], DIS, SA);

        // ---- 3 fused gather layers; last one skips the next-S epilogue ----
        int catBase = b * 96;
        k_gather<1><<<NN / 8, 256>>>(ROW, DEG, CSR, SA, DIS, bc[0], Wc[1], SB,
                                     CAT, catBase);
        k_gather<1><<<NN / 8, 256>>>(ROW, DEG, CSR, SB, DIS, bc[1], Wc[2], SA,
                                     CAT, catBase + 32);
        k_gather<0><<<NN / 8, 256>>>(ROW, DEG, CSR, SA, DIS, bc[2], nullptr,
                                     nullptr, CAT, catBase + 64);
    }

    k_head<<<GG, HIDW>>>(CAT, W1, b1, W2, b2, y, out);
}